// round 2
// baseline (speedup 1.0000x reference)
#include <cuda_runtime.h>
#include <cstdint>

#define NTOT 32768
#define DSUB 128
#define SCB  1024
#define KCB  4
#define MT   128
#define ST   128
#define NCHUNK (SCB/ST)
#define THREADS 256
#define ASTRIDE 129

#define IDX_CNT (NTOT*KCB)            /* 131072  */
#define ZQ_CNT  (NTOT*KCB*DSUB)       /* 16777216 */
#define SC_OFF  (IDX_CNT + 2*ZQ_CNT)  /* 33685504 */

// smem layout (floats): As[128*129] | Bs0[128*128] | Bs1[128*128] | sIdx[128] | Xs[128]
#define SM_AS   0
#define SM_BS0  (MT*ASTRIDE)
#define SM_BS1  (SM_BS0 + DSUB*ST)
#define SM_IDX  (SM_BS1 + DSUB*ST)
#define SM_XS   (SM_IDX + MT)
#define SMEM_FLOATS (SM_XS + MT)
#define SMEM_BYTES  (SMEM_FLOATS*4)

__device__ double g_loss;
__device__ float  g_counts[KCB*SCB];
__device__ float  g_cnorm[KCB*SCB];
__device__ float  g_ct[KCB*DSUB*SCB];   // transposed codebooks: [k][d][s]

__device__ __forceinline__ void cpa16(float* dst, const float* src) {
    unsigned sa = (unsigned)__cvta_generic_to_shared(dst);
    asm volatile("cp.async.cg.shared.global [%0], [%1], 16;" :: "r"(sa), "l"(src));
}

__global__ void init_kernel(const float* __restrict__ cb) {
    int t = blockIdx.x*blockDim.x + threadIdx.x;
    if (t == 0) g_loss = 0.0;
    if (t < KCB*SCB) {
        g_counts[t] = 0.f;
        // ||c||^2: STRICT sequential ascending d, UNFUSED mul+add (XLA elemental reduce)
        const float* r = cb + (size_t)t*DSUB;
        float s = 0.f;
        #pragma unroll 8
        for (int i = 0; i < DSUB; i++) {
            float v = r[i];
            s = __fadd_rn(s, __fmul_rn(v, v));
        }
        g_cnorm[t] = s;
    }
    const int tot = KCB*DSUB*SCB;
    for (int o = t; o < tot; o += blockDim.x*gridDim.x) {
        int s = o & (SCB-1);
        int d = (o >> 10) & (DSUB-1);
        int k = o >> 17;
        g_ct[o] = cb[((k*SCB + s)*DSUB) + d];
    }
}

__global__ __launch_bounds__(THREADS, 1)
void vq_kernel(const float* __restrict__ ze, const float* __restrict__ cb,
               float* __restrict__ out) {
    extern __shared__ float smem[];
    float* As  = smem + SM_AS;
    float* Bs0 = smem + SM_BS0;
    float* Bs1 = smem + SM_BS1;
    int*   sIdx = (int*)(smem + SM_IDX);
    float* Xs  = smem + SM_XS;
    __shared__ float red[8];

    const int k   = blockIdx.y;
    const int n0  = blockIdx.x * MT;
    const int tid = threadIdx.x;
    const int tx  = tid & 15;     // 16 col-groups
    const int ty  = tid >> 4;     // 16 row-groups (8 rows each)

    // ---- kick off B chunk 0 (pre-transposed: conflict-free direct copy) ----
    {
        const float* src = g_ct + (size_t)k*DSUB*SCB;
        for (int t = tid; t < (DSUB*ST)/4; t += THREADS) {
            int d = t >> 5, q = t & 31;
            cpa16(Bs0 + d*ST + q*4, src + d*SCB + q*4);
        }
        asm volatile("cp.async.commit_group;" ::: "memory");
    }
    // ---- load A tile (row-major, stride 129 -> conflict-free STS & LDS) ----
    for (int t = tid; t < MT*DSUB; t += THREADS) {
        int row = t >> 7, d = t & 127;
        As[row*ASTRIDE + d] = ze[(size_t)(n0+row)*512 + k*DSUB + d];
    }
    __syncthreads();

    // ---- X[row] = ||x||^2, STRICT sequential ascending d, UNFUSED (emulate ref) ----
    if (tid < MT) {
        const float* ar = As + tid*ASTRIDE;   // bank = (tid + d) % 32 -> conflict-free
        float s = 0.f;
        #pragma unroll 8
        for (int d = 0; d < DSUB; d++) {
            float v = ar[d];
            s = __fadd_rn(s, __fmul_rn(v, v));
        }
        Xs[tid] = s;
    }
    __syncthreads();

    float Xr[8];
    #pragma unroll
    for (int i = 0; i < 8; i++) Xr[i] = Xs[ty*8 + i];

    float bestV[8];
    int   bestI[8];
    #pragma unroll
    for (int i = 0; i < 8; i++) { bestV[i] = 3.402823466e38f; bestI[i] = 0; }

    const float* cn = g_cnorm + k*SCB;

    for (int c = 0; c < NCHUNK; c++) {
        float* Bc = (c & 1) ? Bs1 : Bs0;
        if (c + 1 < NCHUNK) {
            const float* src = g_ct + (size_t)k*DSUB*SCB + (c+1)*ST;
            float* dstB = ((c+1) & 1) ? Bs1 : Bs0;
            for (int t = tid; t < (DSUB*ST)/4; t += THREADS) {
                int d = t >> 5, q = t & 31;
                cpa16(dstB + d*ST + q*4, src + d*SCB + q*4);
            }
            asm volatile("cp.async.commit_group;" ::: "memory");
            asm volatile("cp.async.wait_group 1;" ::: "memory");
        } else {
            asm volatile("cp.async.wait_group 0;" ::: "memory");
        }
        __syncthreads();

        // preload code norms for this thread's 8 columns
        float cnr[8];
        #pragma unroll
        for (int j = 0; j < 8; j++) {
            int col = (j < 4) ? (4*tx + j) : (64 + 4*tx + (j - 4));
            cnr[j] = cn[c*ST + col];
        }

        unsigned long long acc[8][4];
        #pragma unroll
        for (int i = 0; i < 8; i++)
            #pragma unroll
            for (int p = 0; p < 4; p++) acc[i][p] = 0ULL;

        // dot: single fused-FMA chain per (row,col), ascending kk (emulates Eigen GEMM)
        #pragma unroll 4
        for (int kk = 0; kk < DSUB; kk++) {
            ulonglong2 bA = *(const ulonglong2*)(Bc + kk*ST + 4*tx);
            ulonglong2 bB = *(const ulonglong2*)(Bc + kk*ST + 64 + 4*tx);
            #pragma unroll
            for (int i = 0; i < 8; i++) {
                float a = As[(ty*8 + i)*ASTRIDE + kk];
                unsigned long long ad;
                asm("mov.b64 %0, {%1, %1};" : "=l"(ad) : "f"(a));
                asm("fma.rn.f32x2 %0, %1, %2, %0;" : "+l"(acc[i][0]) : "l"(ad), "l"(bA.x));
                asm("fma.rn.f32x2 %0, %1, %2, %0;" : "+l"(acc[i][1]) : "l"(ad), "l"(bA.y));
                asm("fma.rn.f32x2 %0, %1, %2, %0;" : "+l"(acc[i][2]) : "l"(ad), "l"(bB.x));
                asm("fma.rn.f32x2 %0, %1, %2, %0;" : "+l"(acc[i][3]) : "l"(ad), "l"(bB.y));
            }
        }

        // dist = fl( fl(X - fl(2*G)) + C ), emulating ref's rounding; argmin strict <
        #pragma unroll
        for (int i = 0; i < 8; i++) {
            float Xi = Xr[i];
            #pragma unroll
            for (int p = 0; p < 4; p++) {
                float lo, hi;
                asm("mov.b64 {%0, %1}, %2;" : "=f"(lo), "=f"(hi) : "l"(acc[i][p]));
                int j0 = 2*p;
                int col0 = (j0 < 4) ? (4*tx + j0) : (64 + 4*tx + (j0 - 4));
                int g0 = c*ST + col0;
                float s0 = __fadd_rn(__fsub_rn(Xi, __fmul_rn(2.0f, lo)), cnr[j0]);
                float s1 = __fadd_rn(__fsub_rn(Xi, __fmul_rn(2.0f, hi)), cnr[j0+1]);
                if (s0 < bestV[i]) { bestV[i] = s0; bestI[i] = g0; }
                if (s1 < bestV[i]) { bestV[i] = s1; bestI[i] = g0 + 1; }
            }
        }
        __syncthreads();
    }

    // ---- cross-lane argmin over the 16 col-groups (index tiebreak = lowest) ----
    #pragma unroll
    for (int i = 0; i < 8; i++) {
        float v = bestV[i]; int id = bestI[i];
        #pragma unroll
        for (int off = 1; off < 16; off <<= 1) {
            float vo = __shfl_xor_sync(0xffffffffu, v, off);
            int io   = __shfl_xor_sync(0xffffffffu, id, off);
            if (vo < v || (vo == v && io < id)) { v = vo; id = io; }
        }
        if (tx == 0) {
            int row = ty*8 + i;
            sIdx[row] = id;
            out[(n0 + row)*KCB + k] = (float)id;   // indices_all[n][k]
        }
    }
    __syncthreads();

    if (tid < MT) atomicAdd(&g_counts[k*SCB + sIdx[tid]], 1.0f);

    // ---- epilogue: gather z_q, write both copies, accumulate loss ----
    float lsum = 0.f;
    const float* cbk = cb + (size_t)k*SCB*DSUB;
    float* o_st  = out + IDX_CNT;
    float* o_all = out + IDX_CNT + ZQ_CNT;
    for (int e = tid; e < MT*DSUB; e += THREADS) {
        int row = e >> 7, d = e & 127;
        int idx = sIdx[row];
        float cv = __ldg(cbk + idx*DSUB + d);
        int go = (n0 + row)*512 + k*DSUB + d;
        float a = ze[go];
        float diff = __fsub_rn(cv, a);        // fp32, matches ref rounding
        o_st[go]  = __fadd_rn(a, diff);       // z_q_st = z_e + (z_q - z_e)
        o_all[go] = cv;                       // z_q_all
        lsum += diff*diff;
    }
    #pragma unroll
    for (int off = 16; off > 0; off >>= 1)
        lsum += __shfl_xor_sync(0xffffffffu, lsum, off);
    if ((tid & 31) == 0) red[tid >> 5] = lsum;
    __syncthreads();
    if (tid == 0) {
        float s = 0.f;
        #pragma unroll
        for (int w = 0; w < 8; w++) s += red[w];
        atomicAdd(&g_loss, (double)s);
    }
}

__global__ void fin_kernel(float* __restrict__ out) {
    __shared__ double sh[512];
    int tid = threadIdx.x;
    int k = tid >> 7, j = tid & 127;
    double h = 0.0;
    for (int s = j; s < SCB; s += 128) {
        float cnt = g_counts[k*SCB + s];
        if (cnt > 0.f) {
            double p = (double)cnt / (double)NTOT;
            h -= p * log(p);
        }
    }
    sh[tid] = h;
    __syncthreads();
    for (int off = 64; off > 0; off >>= 1) {
        if (j < off) sh[tid] += sh[tid + off];
        __syncthreads();
    }
    if (tid == 0) {
        double perp = 0.0;
        for (int kk = 0; kk < KCB; kk++) perp += exp(sh[kk*128]);
        perp *= 0.25;
        double loss = g_loss / (double)ZQ_CNT;
        out[SC_OFF + 0] = (float)loss;   // codebook_loss
        out[SC_OFF + 1] = (float)loss;   // commit_loss (same forward value)
        out[SC_OFF + 2] = (float)perp;   // perplexity
    }
}

extern "C" void kernel_launch(void* const* d_in, const int* in_sizes, int n_in,
                              void* d_out, int out_size) {
    const float* ze = (const float*)d_in[0];
    const float* cb = (const float*)d_in[1];
    // defensive: detect swapped input order via element counts
    if (n_in >= 2 && in_sizes[0] == KCB*SCB*DSUB && in_sizes[1] == NTOT*512) {
        const float* t = ze; ze = cb; cb = t;
    }
    float* out = (float*)d_out;
    (void)out_size;

    cudaFuncSetAttribute(vq_kernel, cudaFuncAttributeMaxDynamicSharedMemorySize, SMEM_BYTES);

    init_kernel<<<128, 256>>>(cb);
    vq_kernel<<<dim3(NTOT/MT, KCB), THREADS, SMEM_BYTES>>>(ze, cb, out);
    fin_kernel<<<1, 512>>>(out);
}